// round 8
// baseline (speedup 1.0000x reference)
#include <cuda_runtime.h>
#include <cuda_fp16.h>
#include <cuda_bf16.h>

#define TQ 64
#define TK 128
#define NB 32
#define ND 1024

// Static scratch (no allocations allowed)
__device__ __align__(16) __half g_pq[TQ * NB * ND];
__device__ __align__(16) __half g_pk[TK * NB * ND];
__device__ __align__(16) __half g_vh[ND];
__device__ float  g_probs[NB * TQ * TK];            // [b][tq][k]
__device__ float  g_part[8 * NB * TQ * TK];         // [z][b][tq][k]
__device__ __align__(16) __nv_bfloat16 g_qb[TQ * NB * ND];
__device__ __align__(16) __nv_bfloat16 g_kb[TK * NB * ND];
__device__ __align__(16) __nv_bfloat16 g_wqb[ND * ND];
__device__ __align__(16) __nv_bfloat16 g_wkb[ND * ND];

// ---------------------------------------------------------------------------
// helpers
// ---------------------------------------------------------------------------
__device__ __forceinline__ __half2 htanh2(__half2 x) {
    unsigned xi = *reinterpret_cast<unsigned*>(&x);
    unsigned ri;
    asm("tanh.approx.f16x2 %0, %1;" : "=r"(ri) : "r"(xi));
    return *reinterpret_cast<__half2*>(&ri);
}

__device__ __forceinline__ void ldm_x4(unsigned& r0, unsigned& r1,
                                       unsigned& r2, unsigned& r3,
                                       const void* p) {
    unsigned addr = (unsigned)__cvta_generic_to_shared(p);
    asm volatile("ldmatrix.sync.aligned.m8n8.x4.shared.b16 {%0,%1,%2,%3}, [%4];"
                 : "=r"(r0), "=r"(r1), "=r"(r2), "=r"(r3) : "r"(addr));
}

__device__ __forceinline__ void mma16816(float* c, const unsigned* a,
                                         const unsigned* b) {
    asm volatile(
        "mma.sync.aligned.m16n8k16.row.col.f32.bf16.bf16.f32 "
        "{%0,%1,%2,%3}, {%4,%5,%6,%7}, {%8,%9}, {%0,%1,%2,%3};"
        : "+f"(c[0]), "+f"(c[1]), "+f"(c[2]), "+f"(c[3])
        : "r"(a[0]), "r"(a[1]), "r"(a[2]), "r"(a[3]), "r"(b[0]), "r"(b[1]));
}

__device__ __forceinline__ void cp_async16(void* smem_dst, const void* gsrc) {
    unsigned d = (unsigned)__cvta_generic_to_shared(smem_dst);
    asm volatile("cp.async.cg.shared.global [%0], [%1], 16;" :: "r"(d), "l"(gsrc));
}

// ---------------------------------------------------------------------------
// Kernel A: convert all fp32 inputs to bf16 (one pass)
// ---------------------------------------------------------------------------
__global__ __launch_bounds__(256) void k_convert(const float* __restrict__ q,
                                                 const float* __restrict__ k,
                                                 const float* __restrict__ wq,
                                                 const float* __restrict__ wk) {
    size_t i = (size_t)blockIdx.x * 256 + threadIdx.x;
    const float* src;
    __nv_bfloat16* dst;
    size_t off;
    if (i < 524288)            { src = q;  dst = g_qb;  off = i; }
    else if (i < 1572864)      { src = k;  dst = g_kb;  off = i - 524288; }
    else if (i < 1835008)      { src = wq; dst = g_wqb; off = i - 1572864; }
    else                       { src = wk; dst = g_wkb; off = i - 1835008; }
    float4 f = ((const float4*)src)[off];
    __nv_bfloat162* d2 = (__nv_bfloat162*)(dst + off * 4);
    d2[0] = __floats2bfloat162_rn(f.x, f.y);
    d2[1] = __floats2bfloat162_rn(f.z, f.w);
}

// ---------------------------------------------------------------------------
// Kernel 0: v = linear_att / ||linear_att|| * normalize_scalar  -> fp16
// ---------------------------------------------------------------------------
__global__ void k_prep_v(const float* __restrict__ la,
                         const float* __restrict__ ns) {
    __shared__ float red[256];
    int t = threadIdx.x;
    float s = 0.f;
    for (int i = t; i < ND; i += 256) { float x = la[i]; s += x * x; }
    red[t] = s;
    __syncthreads();
    for (int o = 128; o > 0; o >>= 1) {
        if (t < o) red[t] += red[t + o];
        __syncthreads();
    }
    float scale = ns[0] * rsqrtf(red[0]);
    for (int i = t; i < ND; i += 256) g_vh[i] = __float2half(la[i] * scale);
}

// ---------------------------------------------------------------------------
// Kernel 1: fused dual GEMM, bf16 inputs, 4-stage cp.async pipeline.
// blockIdx.y < 16 -> pq = query@Wq^T + bias ; else pk = keys@Wk^T
// ux0 = u-block offset (split launches for overlap with scores).
// ---------------------------------------------------------------------------
#define GSTRIDE 40   // smem row stride in halves (80B): conflict-free LDSM

__global__ __launch_bounds__(256) void k_gemm2(const float* __restrict__ bias,
                                               int ux0) {
    __shared__ __align__(16) __nv_bfloat16 As[4][128][GSTRIDE];
    __shared__ __align__(16) __nv_bfloat16 Bs[4][128][GSTRIDE];

    int by = blockIdx.y;
    const __nv_bfloat16* A;
    const __nv_bfloat16* W;
    __half* C;
    const float* bptr;
    int m0;
    if (by < 16) { A = g_qb; W = g_wqb; C = g_pq; bptr = bias;    m0 = by * 128; }
    else         { A = g_kb; W = g_wkb; C = g_pk; bptr = nullptr; m0 = (by - 16) * 128; }
    int u0 = (ux0 + blockIdx.x) * 128;

    int t = threadIdx.x;
    int w = t >> 5, lane = t & 31;
    int warpM = (w >> 2) * 64;
    int warpN = (w & 3) * 32;

    float acc[4][4][4];
#pragma unroll
    for (int mi = 0; mi < 4; mi++)
#pragma unroll
        for (int ni = 0; ni < 4; ni++)
#pragma unroll
            for (int i = 0; i < 4; i++) acc[mi][ni][i] = 0.f;

    int lrow = t >> 2, lch = t & 3;
    auto load_tile = [&](int buf, int k0) {
#pragma unroll
        for (int i = 0; i < 2; i++) {
            int row = lrow + i * 64;
            cp_async16(&As[buf][row][lch * 8], A + (size_t)(m0 + row) * 1024 + k0 + lch * 8);
            cp_async16(&Bs[buf][row][lch * 8], W + (size_t)(u0 + row) * 1024 + k0 + lch * 8);
        }
        asm volatile("cp.async.commit_group;");
    };

    load_tile(0, 0);
    load_tile(1, 32);
    load_tile(2, 64);

    int buf = 0;
    for (int it = 0; it < 32; it++) {
        if (it < 30) asm volatile("cp.async.wait_group 2;");
        else         asm volatile("cp.async.wait_group 0;");
        __syncthreads();

        if (it + 3 < 32) load_tile((buf + 3) & 3, (it + 3) * 32);

#pragma unroll
        for (int kk = 0; kk < 2; kk++) {
            unsigned a[4][4];
            int arow_l = lane & 15;
            int acol = kk * 16 + (lane >> 4) * 8;
#pragma unroll
            for (int mi = 0; mi < 4; mi++) {
                ldm_x4(a[mi][0], a[mi][1], a[mi][2], a[mi][3],
                       &As[buf][warpM + mi * 16 + arow_l][acol]);
            }
            unsigned b[4][2];
            int brow_l = ((lane >> 4) & 1) * 8 + (lane & 7);
            int bcol = kk * 16 + ((lane >> 3) & 1) * 8;
#pragma unroll
            for (int np = 0; np < 2; np++) {
                unsigned r0, r1, r2, r3;
                ldm_x4(r0, r1, r2, r3, &Bs[buf][warpN + np * 16 + brow_l][bcol]);
                b[np * 2][0] = r0; b[np * 2][1] = r1;
                b[np * 2 + 1][0] = r2; b[np * 2 + 1][1] = r3;
            }
#pragma unroll
            for (int mi = 0; mi < 4; mi++)
#pragma unroll
                for (int ni = 0; ni < 4; ni++)
                    mma16816(acc[mi][ni], a[mi], b[ni]);
        }
        buf = (buf + 1) & 3;
    }

    // epilogue: +bias, convert to fp16, store
    int g = lane >> 2, tig = lane & 3;
#pragma unroll
    for (int mi = 0; mi < 4; mi++) {
#pragma unroll
        for (int ni = 0; ni < 4; ni++) {
            int r = m0 + warpM + mi * 16 + g;
            int c = u0 + warpN + ni * 8 + tig * 2;
            float b0 = 0.f, b1 = 0.f;
            if (bptr) { b0 = __ldg(bptr + c); b1 = __ldg(bptr + c + 1); }
            *(__half2*)(C + (size_t)r * 1024 + c) =
                __floats2half2_rn(acc[mi][ni][0] + b0, acc[mi][ni][1] + b1);
            *(__half2*)(C + (size_t)(r + 8) * 1024 + c) =
                __floats2half2_rn(acc[mi][ni][2] + b0, acc[mi][ni][3] + b1);
        }
    }
}

// ---------------------------------------------------------------------------
// Kernel 2: partial scores (round-6 shape). grid (TQ/8, NB, 4); z = zbase+bz.
// partial[z][b][q][k] = sum_{u in 128-slice} tanh(pq+pk) * v
// ---------------------------------------------------------------------------
__global__ __launch_bounds__(256, 4) void k_scores3(int zbase) {
    __shared__ __align__(16) __half2 pk_s[64 * 129];  // [uu][k], pad 129
    __shared__ __align__(16) __half2 pq_s[64 * 12];   // [uu][q], pad 12 (16B align)
    __shared__ __half2 v_s[64];

    int t = threadIdx.x, w = t >> 5, lane = t & 31;
    int bb = blockIdx.y;
    int qt0 = blockIdx.x * 8;
    int z = zbase + blockIdx.z;
    int u0 = z * 128;
    int kidx = (w & 3) * 32 + lane;
    int qb = (w >> 2) * 4;

    // load pk slice: 128 tk x 128 u halves, transposed to [uu][k]
#pragma unroll
    for (int i = 0; i < 8; i++) {
        int pos = t + i * 256;
        int u4 = pos & 15, tk = pos >> 4;
        uint4 d = *(const uint4*)(g_pk + (size_t)(tk * NB + bb) * 1024 + u0 + u4 * 8);
        const __half2* h = (const __half2*)&d;
#pragma unroll
        for (int j = 0; j < 4; j++) pk_s[(u4 * 4 + j) * 129 + tk] = h[j];
    }
    if (t < 128) {
        int u4 = t & 15, q = t >> 4;
        uint4 d = *(const uint4*)(g_pq + (size_t)((qt0 + q) * NB + bb) * 1024 + u0 + u4 * 8);
        const __half2* h = (const __half2*)&d;
#pragma unroll
        for (int j = 0; j < 4; j++) pq_s[(u4 * 4 + j) * 12 + q] = h[j];
    }
    if (t < 64) v_s[t] = ((const __half2*)g_vh)[u0 / 2 + t];
    __syncthreads();

    __half2 acc2[4];
#pragma unroll
    for (int j = 0; j < 4; j++) acc2[j] = __float2half2_rn(0.f);

#pragma unroll 8
    for (int uu = 0; uu < 64; uu++) {
        __half2 pk2 = pk_s[uu * 129 + kidx];
        __half2 v2 = v_s[uu];
        uint4 pq4 = *(const uint4*)&pq_s[uu * 12 + qb];   // LDS.128, broadcast
        const __half2* pqh = (const __half2*)&pq4;
#pragma unroll
        for (int j = 0; j < 4; j++) {
            __half2 a = __hadd2(pqh[j], pk2);
            acc2[j] = __hfma2(htanh2(a), v2, acc2[j]);
        }
    }

#pragma unroll
    for (int j = 0; j < 4; j++) {
        int q = qt0 + qb + j;
        g_part[(((size_t)z * NB + bb) * TQ + q) * TK + kidx] =
            __low2float(acc2[j]) + __high2float(acc2[j]);
    }
}

// ---------------------------------------------------------------------------
// Kernel 2b: reduce partials + softmax. grid (TQ/8, NB), warp w -> q = bx*8+w
// ---------------------------------------------------------------------------
__global__ __launch_bounds__(256) void k_softmax(int has_scores,
                                                 float* __restrict__ scores_out) {
    int t = threadIdx.x, w = t >> 5, lane = t & 31;
    int bb = blockIdx.y;
    int q = blockIdx.x * 8 + w;

    float x[4];
#pragma unroll
    for (int jj = 0; jj < 4; jj++) {
        int k = lane + jj * 32;
        float s = 0.f;
#pragma unroll
        for (int z = 0; z < 8; z++)
            s += g_part[(((size_t)z * NB + bb) * TQ + q) * TK + k];
        x[jj] = s;
    }
    float m = fmaxf(fmaxf(x[0], x[1]), fmaxf(x[2], x[3]));
#pragma unroll
    for (int o = 16; o > 0; o >>= 1) m = fmaxf(m, __shfl_xor_sync(0xffffffffu, m, o));
    float e0 = __expf(x[0] - m), e1 = __expf(x[1] - m);
    float e2 = __expf(x[2] - m), e3 = __expf(x[3] - m);
    float s = e0 + e1 + e2 + e3;
#pragma unroll
    for (int o = 16; o > 0; o >>= 1) s += __shfl_xor_sync(0xffffffffu, s, o);
    float inv = __fdividef(1.f, s);
    float p0 = e0 * inv, p1 = e1 * inv, p2 = e2 * inv, p3 = e3 * inv;

    float* pp = g_probs + ((size_t)bb * TQ + q) * TK;
    pp[lane] = p0; pp[lane + 32] = p1; pp[lane + 64] = p2; pp[lane + 96] = p3;

    if (has_scores) {
        float* so = scores_out + ((size_t)q * NB + bb) * TK;
        so[lane] = p0; so[lane + 32] = p1; so[lane + 64] = p2; so[lane + 96] = p3;
    }
}

// ---------------------------------------------------------------------------
// Kernel 3: context[tq][b][n] = sum_k probs[b][tq][k] * keys[k][b][n]
// grid (TQ/8, NB): 8 q per block, 256 threads each own 4 n (float4).
// ---------------------------------------------------------------------------
__global__ __launch_bounds__(256) void k_context(const float* __restrict__ keys,
                                                 float* __restrict__ ctx) {
    __shared__ float p_s[8 * 128];
    int t = threadIdx.x;
    int bb = blockIdx.y, qt0 = blockIdx.x * 8;

#pragma unroll
    for (int i = 0; i < 4; i++) {
        int pos = t + i * 256;
        int qq = pos >> 7, k = pos & 127;
        p_s[pos] = g_probs[((size_t)bb * TQ + qt0 + qq) * TK + k];
    }
    __syncthreads();

    float4 acc[8];
#pragma unroll
    for (int qq = 0; qq < 8; qq++) acc[qq] = make_float4(0.f, 0.f, 0.f, 0.f);

    for (int tk = 0; tk < 128; tk++) {
        float4 kv = *(const float4*)(keys + ((size_t)tk * NB + bb) * 1024 + t * 4);
#pragma unroll
        for (int qq = 0; qq < 8; qq++) {
            float pv = p_s[qq * 128 + tk];
            acc[qq].x += pv * kv.x;
            acc[qq].y += pv * kv.y;
            acc[qq].z += pv * kv.z;
            acc[qq].w += pv * kv.w;
        }
    }
#pragma unroll
    for (int qq = 0; qq < 8; qq++) {
        *(float4*)(ctx + ((size_t)(qt0 + qq) * NB + bb) * 1024 + t * 4) = acc[qq];
    }
}

// ---------------------------------------------------------------------------
extern "C" void kernel_launch(void* const* d_in, const int* in_sizes, int n_in,
                              void* d_out, int out_size) {
    const float* query = (const float*)d_in[0];
    const float* keys  = (const float*)d_in[1];
    const float* Wq    = (const float*)d_in[2];
    const float* Wk    = (const float*)d_in[3];
    const float* la    = (const float*)d_in[4];
    const float* ns    = (const float*)d_in[5];
    const float* nbias = (const float*)d_in[6];

    float* ctx = (float*)d_out;
    const int ctx_elems = TQ * NB * ND;
    const int scr_elems = TQ * NB * TK;
    int has_scores = (out_size >= ctx_elems + scr_elems) ? 1 : 0;
    float* scores = ctx + ctx_elems;

    // One-time side-stream/event setup (execution resources, not device memory;
    // same launch sequence is issued on every call -> graph-deterministic).
    static cudaStream_t s_side = nullptr;
    static cudaEvent_t ev0 = nullptr, evP = nullptr, evG1 = nullptr, evG2 = nullptr;
    static int s_init = 0;
    if (!s_init) {
        if (cudaStreamCreateWithFlags(&s_side, cudaStreamNonBlocking) != cudaSuccess)
            s_side = nullptr;
        cudaEventCreateWithFlags(&ev0,  cudaEventDisableTiming);
        cudaEventCreateWithFlags(&evP,  cudaEventDisableTiming);
        cudaEventCreateWithFlags(&evG1, cudaEventDisableTiming);
        cudaEventCreateWithFlags(&evG2, cudaEventDisableTiming);
        s_init = 1;
    }
    cudaStream_t side = s_side ? s_side : (cudaStream_t)0;
    cudaStream_t main = (cudaStream_t)0;

    // fork: prep_v on side stream (tiny, independent of convert/gemm)
    cudaEventRecord(ev0, main);
    cudaStreamWaitEvent(side, ev0, 0);
    k_prep_v<<<1, 256, 0, side>>>(la, ns);
    cudaEventRecord(evP, side);

    // main: convert then GEMM u-half 1 (u blocks 0..3)
    k_convert<<<8192, 256, 0, main>>>(query, keys, Wq, Wk);
    k_gemm2<<<dim3(4, 48), 256, 0, main>>>(nbias, 0);
    cudaEventRecord(evG1, main);

    // side: GEMM u-half 2 (u blocks 4..7), concurrent with scores half 1
    cudaStreamWaitEvent(side, evG1, 0);
    k_gemm2<<<dim3(4, 48), 256, 0, side>>>(nbias, 4);
    cudaEventRecord(evG2, side);

    // main: scores half 1 (z 0..3) — needs gemm half 1 (+ prep_v)
    cudaStreamWaitEvent(main, evP, 0);
    k_scores3<<<dim3(TQ / 8, NB, 4), 256, 0, main>>>(0);

    // main: scores half 2 (z 4..7) — needs gemm half 2
    cudaStreamWaitEvent(main, evG2, 0);
    k_scores3<<<dim3(TQ / 8, NB, 4), 256, 0, main>>>(4);

    k_softmax<<<dim3(TQ / 8, NB), 256, 0, main>>>(has_scores, scores);
    k_context<<<dim3(TQ / 8, NB), 256, 0, main>>>(keys, ctx);
}

// round 9
// speedup vs baseline: 1.1255x; 1.1255x over previous
#include <cuda_runtime.h>
#include <cuda_fp16.h>
#include <cuda_bf16.h>

#define TQ 64
#define TK 128
#define NB 32
#define ND 1024

// Static scratch (no allocations allowed)
__device__ __align__(16) __half g_pq[TQ * NB * ND];
__device__ __align__(16) __half g_pk[TK * NB * ND];
__device__ __align__(16) __half g_vh[ND];
__device__ float  g_probs[NB * TQ * TK];            // [b][tq][k]
__device__ float  g_part[8 * NB * TQ * TK];         // [z][b][tq][k]
__device__ __align__(16) __nv_bfloat16 g_qb[TQ * NB * ND];
__device__ __align__(16) __nv_bfloat16 g_kb[TK * NB * ND];
__device__ __align__(16) __nv_bfloat16 g_wqb[ND * ND];
__device__ __align__(16) __nv_bfloat16 g_wkb[ND * ND];

// ---------------------------------------------------------------------------
// helpers
// ---------------------------------------------------------------------------
__device__ __forceinline__ __half2 htanh2(__half2 x) {
    unsigned xi = *reinterpret_cast<unsigned*>(&x);
    unsigned ri;
    asm("tanh.approx.f16x2 %0, %1;" : "=r"(ri) : "r"(xi));
    return *reinterpret_cast<__half2*>(&ri);
}

__device__ __forceinline__ void ldm_x4(unsigned& r0, unsigned& r1,
                                       unsigned& r2, unsigned& r3,
                                       const void* p) {
    unsigned addr = (unsigned)__cvta_generic_to_shared(p);
    asm volatile("ldmatrix.sync.aligned.m8n8.x4.shared.b16 {%0,%1,%2,%3}, [%4];"
                 : "=r"(r0), "=r"(r1), "=r"(r2), "=r"(r3) : "r"(addr));
}

__device__ __forceinline__ void mma16816(float* c, const unsigned* a,
                                         const unsigned* b) {
    asm volatile(
        "mma.sync.aligned.m16n8k16.row.col.f32.bf16.bf16.f32 "
        "{%0,%1,%2,%3}, {%4,%5,%6,%7}, {%8,%9}, {%0,%1,%2,%3};"
        : "+f"(c[0]), "+f"(c[1]), "+f"(c[2]), "+f"(c[3])
        : "r"(a[0]), "r"(a[1]), "r"(a[2]), "r"(a[3]), "r"(b[0]), "r"(b[1]));
}

__device__ __forceinline__ void cp_async16(void* smem_dst, const void* gsrc) {
    unsigned d = (unsigned)__cvta_generic_to_shared(smem_dst);
    asm volatile("cp.async.cg.shared.global [%0], [%1], 16;" :: "r"(d), "l"(gsrc));
}

// ---------------------------------------------------------------------------
// Kernel A: convert all fp32 inputs to bf16 (one pass)
// ---------------------------------------------------------------------------
__global__ __launch_bounds__(256) void k_convert(const float* __restrict__ q,
                                                 const float* __restrict__ k,
                                                 const float* __restrict__ wq,
                                                 const float* __restrict__ wk) {
    size_t i = (size_t)blockIdx.x * 256 + threadIdx.x;
    const float* src;
    __nv_bfloat16* dst;
    size_t off;
    if (i < 524288)            { src = q;  dst = g_qb;  off = i; }
    else if (i < 1572864)      { src = k;  dst = g_kb;  off = i - 524288; }
    else if (i < 1835008)      { src = wq; dst = g_wqb; off = i - 1572864; }
    else                       { src = wk; dst = g_wkb; off = i - 1835008; }
    float4 f = ((const float4*)src)[off];
    __nv_bfloat162* d2 = (__nv_bfloat162*)(dst + off * 4);
    d2[0] = __floats2bfloat162_rn(f.x, f.y);
    d2[1] = __floats2bfloat162_rn(f.z, f.w);
}

// ---------------------------------------------------------------------------
// Kernel 0: v = linear_att / ||linear_att|| * normalize_scalar  -> fp16
// ---------------------------------------------------------------------------
__global__ void k_prep_v(const float* __restrict__ la,
                         const float* __restrict__ ns) {
    __shared__ float red[256];
    int t = threadIdx.x;
    float s = 0.f;
    for (int i = t; i < ND; i += 256) { float x = la[i]; s += x * x; }
    red[t] = s;
    __syncthreads();
    for (int o = 128; o > 0; o >>= 1) {
        if (t < o) red[t] += red[t + o];
        __syncthreads();
    }
    float scale = ns[0] * rsqrtf(red[0]);
    for (int i = t; i < ND; i += 256) g_vh[i] = __float2half(la[i] * scale);
}

// ---------------------------------------------------------------------------
// Kernel 1: fused dual GEMM, bf16 inputs, BK=64, 3-stage cp.async pipeline.
// blockIdx.y < 16 -> pq = query@Wq^T + bias ; else pk = keys@Wk^T
// block tile 128x128x64, 8 warps (warp tile 64x32); 16 barriers total.
// ---------------------------------------------------------------------------
#define GSTRIDE 72   // smem row stride in halves (144B): conflict-free LDSM

__global__ __launch_bounds__(256) void k_gemm3(const float* __restrict__ bias) {
    __shared__ __align__(16) __nv_bfloat16 As[3][128][GSTRIDE];
    __shared__ __align__(16) __nv_bfloat16 Bs[3][128][GSTRIDE];

    int by = blockIdx.y;
    const __nv_bfloat16* A;
    const __nv_bfloat16* W;
    __half* C;
    const float* bptr;
    int m0;
    if (by < 16) { A = g_qb; W = g_wqb; C = g_pq; bptr = bias;    m0 = by * 128; }
    else         { A = g_kb; W = g_wkb; C = g_pk; bptr = nullptr; m0 = (by - 16) * 128; }
    int u0 = blockIdx.x * 128;

    int t = threadIdx.x;
    int w = t >> 5, lane = t & 31;
    int warpM = (w >> 2) * 64;
    int warpN = (w & 3) * 32;

    float acc[4][4][4];
#pragma unroll
    for (int mi = 0; mi < 4; mi++)
#pragma unroll
        for (int ni = 0; ni < 4; ni++)
#pragma unroll
            for (int i = 0; i < 4; i++) acc[mi][ni][i] = 0.f;

    // loader: 128 rows x 64 K bf16 = 128 rows x 8 chunks(16B) per operand
    int lrow = t >> 3, lch = t & 7;   // 32 rows per pass, 4 passes
    auto load_tile = [&](int buf, int k0) {
#pragma unroll
        for (int i = 0; i < 4; i++) {
            int row = lrow + i * 32;
            cp_async16(&As[buf][row][lch * 8], A + (size_t)(m0 + row) * 1024 + k0 + lch * 8);
            cp_async16(&Bs[buf][row][lch * 8], W + (size_t)(u0 + row) * 1024 + k0 + lch * 8);
        }
        asm volatile("cp.async.commit_group;");
    };

    load_tile(0, 0);
    load_tile(1, 64);

    int buf = 0;
    for (int it = 0; it < 16; it++) {
        if (it < 15) asm volatile("cp.async.wait_group 1;");
        else         asm volatile("cp.async.wait_group 0;");
        __syncthreads();

        if (it + 2 < 16) load_tile((buf + 2) % 3, (it + 2) * 64);

#pragma unroll
        for (int kk = 0; kk < 4; kk++) {
            unsigned a[4][4];
            int arow_l = lane & 15;
            int acol = kk * 16 + (lane >> 4) * 8;
#pragma unroll
            for (int mi = 0; mi < 4; mi++) {
                ldm_x4(a[mi][0], a[mi][1], a[mi][2], a[mi][3],
                       &As[buf][warpM + mi * 16 + arow_l][acol]);
            }
            unsigned b[4][2];
            int brow_l = ((lane >> 4) & 1) * 8 + (lane & 7);
            int bcol = kk * 16 + ((lane >> 3) & 1) * 8;
#pragma unroll
            for (int np = 0; np < 2; np++) {
                unsigned r0, r1, r2, r3;
                ldm_x4(r0, r1, r2, r3, &Bs[buf][warpN + np * 16 + brow_l][bcol]);
                b[np * 2][0] = r0; b[np * 2][1] = r1;
                b[np * 2 + 1][0] = r2; b[np * 2 + 1][1] = r3;
            }
#pragma unroll
            for (int mi = 0; mi < 4; mi++)
#pragma unroll
                for (int ni = 0; ni < 4; ni++)
                    mma16816(acc[mi][ni], a[mi], b[ni]);
        }
        buf = (buf + 1) % 3;
        if (buf == 3) buf = 0;
    }

    // epilogue: +bias, convert to fp16, store
    int g = lane >> 2, tig = lane & 3;
#pragma unroll
    for (int mi = 0; mi < 4; mi++) {
#pragma unroll
        for (int ni = 0; ni < 4; ni++) {
            int r = m0 + warpM + mi * 16 + g;
            int c = u0 + warpN + ni * 8 + tig * 2;
            float b0 = 0.f, b1 = 0.f;
            if (bptr) { b0 = __ldg(bptr + c); b1 = __ldg(bptr + c + 1); }
            *(__half2*)(C + (size_t)r * 1024 + c) =
                __floats2half2_rn(acc[mi][ni][0] + b0, acc[mi][ni][1] + b1);
            *(__half2*)(C + (size_t)(r + 8) * 1024 + c) =
                __floats2half2_rn(acc[mi][ni][2] + b0, acc[mi][ni][3] + b1);
        }
    }
}

// ---------------------------------------------------------------------------
// Kernel 2: partial scores. grid (TQ/8, NB, 8); blockIdx.z = 128-u slice.
// partial[z][b][q][k] = sum_{u in slice} tanh(pq+pk) * v  (tanh.approx.f16x2)
// ---------------------------------------------------------------------------
__global__ __launch_bounds__(256, 4) void k_scores3() {
    __shared__ __align__(16) __half2 pk_s[64 * 129];  // [uu][k], pad 129
    __shared__ __align__(16) __half2 pq_s[64 * 12];   // [uu][q], pad 12 (16B align)
    __shared__ __half2 v_s[64];

    int t = threadIdx.x, w = t >> 5, lane = t & 31;
    int bb = blockIdx.y;
    int qt0 = blockIdx.x * 8;
    int z = blockIdx.z;
    int u0 = z * 128;
    int kidx = (w & 3) * 32 + lane;
    int qb = (w >> 2) * 4;

    // load pk slice: 128 tk x 128 u halves, transposed to [uu][k]
#pragma unroll
    for (int i = 0; i < 8; i++) {
        int pos = t + i * 256;
        int u4 = pos & 15, tk = pos >> 4;
        uint4 d = *(const uint4*)(g_pk + (size_t)(tk * NB + bb) * 1024 + u0 + u4 * 8);
        const __half2* h = (const __half2*)&d;
#pragma unroll
        for (int j = 0; j < 4; j++) pk_s[(u4 * 4 + j) * 129 + tk] = h[j];
    }
    if (t < 128) {
        int u4 = t & 15, q = t >> 4;
        uint4 d = *(const uint4*)(g_pq + (size_t)((qt0 + q) * NB + bb) * 1024 + u0 + u4 * 8);
        const __half2* h = (const __half2*)&d;
#pragma unroll
        for (int j = 0; j < 4; j++) pq_s[(u4 * 4 + j) * 12 + q] = h[j];
    }
    if (t < 64) v_s[t] = ((const __half2*)g_vh)[u0 / 2 + t];
    __syncthreads();

    __half2 acc2[4];
#pragma unroll
    for (int j = 0; j < 4; j++) acc2[j] = __float2half2_rn(0.f);

#pragma unroll 8
    for (int uu = 0; uu < 64; uu++) {
        __half2 pk2 = pk_s[uu * 129 + kidx];
        __half2 v2 = v_s[uu];
        uint4 pq4 = *(const uint4*)&pq_s[uu * 12 + qb];   // LDS.128, broadcast
        const __half2* pqh = (const __half2*)&pq4;
#pragma unroll
        for (int j = 0; j < 4; j++) {
            __half2 a = __hadd2(pqh[j], pk2);
            acc2[j] = __hfma2(htanh2(a), v2, acc2[j]);
        }
    }

#pragma unroll
    for (int j = 0; j < 4; j++) {
        int q = qt0 + qb + j;
        g_part[(((size_t)z * NB + bb) * TQ + q) * TK + kidx] =
            __low2float(acc2[j]) + __high2float(acc2[j]);
    }
}

// ---------------------------------------------------------------------------
// Kernel 2b: reduce partials + softmax. grid (TQ/8, NB), warp w -> q = bx*8+w
// ---------------------------------------------------------------------------
__global__ __launch_bounds__(256) void k_softmax(int has_scores,
                                                 float* __restrict__ scores_out) {
    int t = threadIdx.x, w = t >> 5, lane = t & 31;
    int bb = blockIdx.y;
    int q = blockIdx.x * 8 + w;

    float x[4];
#pragma unroll
    for (int jj = 0; jj < 4; jj++) {
        int k = lane + jj * 32;
        float s = 0.f;
#pragma unroll
        for (int z = 0; z < 8; z++)
            s += g_part[(((size_t)z * NB + bb) * TQ + q) * TK + k];
        x[jj] = s;
    }
    float m = fmaxf(fmaxf(x[0], x[1]), fmaxf(x[2], x[3]));
#pragma unroll
    for (int o = 16; o > 0; o >>= 1) m = fmaxf(m, __shfl_xor_sync(0xffffffffu, m, o));
    float e0 = __expf(x[0] - m), e1 = __expf(x[1] - m);
    float e2 = __expf(x[2] - m), e3 = __expf(x[3] - m);
    float s = e0 + e1 + e2 + e3;
#pragma unroll
    for (int o = 16; o > 0; o >>= 1) s += __shfl_xor_sync(0xffffffffu, s, o);
    float inv = __fdividef(1.f, s);
    float p0 = e0 * inv, p1 = e1 * inv, p2 = e2 * inv, p3 = e3 * inv;

    float* pp = g_probs + ((size_t)bb * TQ + q) * TK;
    pp[lane] = p0; pp[lane + 32] = p1; pp[lane + 64] = p2; pp[lane + 96] = p3;

    if (has_scores) {
        float* so = scores_out + ((size_t)q * NB + bb) * TK;
        so[lane] = p0; so[lane + 32] = p1; so[lane + 64] = p2; so[lane + 96] = p3;
    }
}

// ---------------------------------------------------------------------------
// Kernel 3: context[tq][b][n] = sum_k probs[b][tq][k] * keys[k][b][n]
// grid (TQ/8, NB): 8 q per block, 256 threads each own 4 n (float4).
// ---------------------------------------------------------------------------
__global__ __launch_bounds__(256) void k_context(const float* __restrict__ keys,
                                                 float* __restrict__ ctx) {
    __shared__ float p_s[8 * 128];
    int t = threadIdx.x;
    int bb = blockIdx.y, qt0 = blockIdx.x * 8;

#pragma unroll
    for (int i = 0; i < 4; i++) {
        int pos = t + i * 256;
        int qq = pos >> 7, k = pos & 127;
        p_s[pos] = g_probs[((size_t)bb * TQ + qt0 + qq) * TK + k];
    }
    __syncthreads();

    float4 acc[8];
#pragma unroll
    for (int qq = 0; qq < 8; qq++) acc[qq] = make_float4(0.f, 0.f, 0.f, 0.f);

    for (int tk = 0; tk < 128; tk++) {
        float4 kv = *(const float4*)(keys + ((size_t)tk * NB + bb) * 1024 + t * 4);
#pragma unroll
        for (int qq = 0; qq < 8; qq++) {
            float pv = p_s[qq * 128 + tk];
            acc[qq].x += pv * kv.x;
            acc[qq].y += pv * kv.y;
            acc[qq].z += pv * kv.z;
            acc[qq].w += pv * kv.w;
        }
    }
#pragma unroll
    for (int qq = 0; qq < 8; qq++) {
        *(float4*)(ctx + ((size_t)(qt0 + qq) * NB + bb) * 1024 + t * 4) = acc[qq];
    }
}

// ---------------------------------------------------------------------------
extern "C" void kernel_launch(void* const* d_in, const int* in_sizes, int n_in,
                              void* d_out, int out_size) {
    const float* query = (const float*)d_in[0];
    const float* keys  = (const float*)d_in[1];
    const float* Wq    = (const float*)d_in[2];
    const float* Wk    = (const float*)d_in[3];
    const float* la    = (const float*)d_in[4];
    const float* ns    = (const float*)d_in[5];
    const float* nbias = (const float*)d_in[6];

    float* ctx = (float*)d_out;
    const int ctx_elems = TQ * NB * ND;
    const int scr_elems = TQ * NB * TK;
    int has_scores = (out_size >= ctx_elems + scr_elems) ? 1 : 0;
    float* scores = ctx + ctx_elems;

    k_convert<<<8192, 256>>>(query, keys, Wq, Wk);
    k_prep_v<<<1, 256>>>(la, ns);

    k_gemm3<<<dim3(ND / 128, 48), 256>>>(nbias);

    k_scores3<<<dim3(TQ / 8, NB, 8), 256>>>();
    k_softmax<<<dim3(TQ / 8, NB), 256>>>(has_scores, scores);

    k_context<<<dim3(TQ / 8, NB), 256>>>(keys, ctx);
}

// round 10
// speedup vs baseline: 1.2137x; 1.0783x over previous
#include <cuda_runtime.h>
#include <cuda_fp16.h>
#include <cuda_bf16.h>

#define TQ 64
#define TK 128
#define NB 32
#define ND 1024

// Static scratch (no allocations allowed)
__device__ __align__(16) __half g_pq[TQ * NB * ND];
__device__ __align__(16) __half g_pk[TK * NB * ND];
__device__ __align__(16) __half g_vh[ND];
__device__ float  g_part[8 * NB * TQ * TK];         // [z][b][tq][k]
__device__ __align__(16) __nv_bfloat16 g_qb[TQ * NB * ND];
__device__ __align__(16) __nv_bfloat16 g_kb[TK * NB * ND];
__device__ __align__(16) __nv_bfloat16 g_wqb[ND * ND];
__device__ __align__(16) __nv_bfloat16 g_wkb[ND * ND];

// ---------------------------------------------------------------------------
// helpers
// ---------------------------------------------------------------------------
__device__ __forceinline__ __half2 htanh2(__half2 x) {
    unsigned xi = *reinterpret_cast<unsigned*>(&x);
    unsigned ri;
    asm("tanh.approx.f16x2 %0, %1;" : "=r"(ri) : "r"(xi));
    return *reinterpret_cast<__half2*>(&ri);
}

// Pade [7/6] tanh on FMA/ALU pipes (no MUFU). Coeffs scaled by 8/135135.
// Exact to ~1.5e-5 at |x|=4 (math); fp16 eval noise ~5e-4 (same order as
// tanh.approx.f16). Clamp to +-4: tanh(4)=0.99933.
__device__ __forceinline__ __half2 ptanh2(__half2 x) {
    x = __hmin2(__hmax2(x, __float2half2_rn(-4.0f)), __float2half2_rn(4.0f));
    __half2 t = __hmul2(x, x);
    __half2 p = __hfma2(__float2half2_rn(5.92008e-5f), t,
                        __float2half2_rn(2.237786e-2f));
    p = __hfma2(p, t, __float2half2_rn(1.0256410f));
    p = __hfma2(p, t, __float2half2_rn(8.0f));
    p = __hmul2(p, x);                                   // numerator
    __half2 qn = __hfma2(__float2half2_rn(-1.657604e-3f), t,
                         __float2half2_rn(-0.18648246f));
    qn = __hfma2(qn, t, __float2half2_rn(-3.6923077f));
    qn = __hfma2(qn, t, __float2half2_rn(-8.0f));        // -denominator
    unsigned dpos = (*reinterpret_cast<unsigned*>(&qn)) ^ 0x80008000u;
    unsigned r0b = __vsub2(0x78007800u, dpos);           // ~1/den bit trick
    __half2 r = *reinterpret_cast<__half2*>(&r0b);
    const __half2 two = __float2half2_rn(2.0f);
    r = __hmul2(r, __hfma2(qn, r, two));                 // Newton 1
    r = __hmul2(r, __hfma2(qn, r, two));                 // Newton 2
    return __hmul2(p, r);
}

__device__ __forceinline__ void ldm_x4(unsigned& r0, unsigned& r1,
                                       unsigned& r2, unsigned& r3,
                                       const void* p) {
    unsigned addr = (unsigned)__cvta_generic_to_shared(p);
    asm volatile("ldmatrix.sync.aligned.m8n8.x4.shared.b16 {%0,%1,%2,%3}, [%4];"
                 : "=r"(r0), "=r"(r1), "=r"(r2), "=r"(r3) : "r"(addr));
}

__device__ __forceinline__ void mma16816(float* c, const unsigned* a,
                                         const unsigned* b) {
    asm volatile(
        "mma.sync.aligned.m16n8k16.row.col.f32.bf16.bf16.f32 "
        "{%0,%1,%2,%3}, {%4,%5,%6,%7}, {%8,%9}, {%0,%1,%2,%3};"
        : "+f"(c[0]), "+f"(c[1]), "+f"(c[2]), "+f"(c[3])
        : "r"(a[0]), "r"(a[1]), "r"(a[2]), "r"(a[3]), "r"(b[0]), "r"(b[1]));
}

__device__ __forceinline__ void cp_async16(void* smem_dst, const void* gsrc) {
    unsigned d = (unsigned)__cvta_generic_to_shared(smem_dst);
    asm volatile("cp.async.cg.shared.global [%0], [%1], 16;" :: "r"(d), "l"(gsrc));
}

// ---------------------------------------------------------------------------
// Kernel A: convert all fp32 inputs to bf16; last block also preps v.
// ---------------------------------------------------------------------------
__global__ __launch_bounds__(256) void k_convert(const float* __restrict__ q,
                                                 const float* __restrict__ k,
                                                 const float* __restrict__ wq,
                                                 const float* __restrict__ wk,
                                                 const float* __restrict__ la,
                                                 const float* __restrict__ ns) {
    if (blockIdx.x == 8192) {
        // prep v = la / ||la|| * ns  -> fp16
        __shared__ float red[256];
        int t = threadIdx.x;
        float s = 0.f;
        for (int i = t; i < ND; i += 256) { float x = la[i]; s += x * x; }
        red[t] = s;
        __syncthreads();
        for (int o = 128; o > 0; o >>= 1) {
            if (t < o) red[t] += red[t + o];
            __syncthreads();
        }
        float scale = ns[0] * rsqrtf(red[0]);
        for (int i = t; i < ND; i += 256) g_vh[i] = __float2half(la[i] * scale);
        return;
    }
    size_t i = (size_t)blockIdx.x * 256 + threadIdx.x;
    const float* src;
    __nv_bfloat16* dst;
    size_t off;
    if (i < 524288)            { src = q;  dst = g_qb;  off = i; }
    else if (i < 1572864)      { src = k;  dst = g_kb;  off = i - 524288; }
    else if (i < 1835008)      { src = wq; dst = g_wqb; off = i - 1572864; }
    else                       { src = wk; dst = g_wkb; off = i - 1835008; }
    float4 f = ((const float4*)src)[off];
    __nv_bfloat162* d2 = (__nv_bfloat162*)(dst + off * 4);
    d2[0] = __floats2bfloat162_rn(f.x, f.y);
    d2[1] = __floats2bfloat162_rn(f.z, f.w);
}

// ---------------------------------------------------------------------------
// Kernel 1: fused dual GEMM, bf16 inputs, BK=64, 3-stage cp.async pipeline.
// ---------------------------------------------------------------------------
#define GSTRIDE 72   // smem row stride in halves (144B): conflict-free LDSM

__global__ __launch_bounds__(256) void k_gemm3(const float* __restrict__ bias) {
    __shared__ __align__(16) __nv_bfloat16 As[3][128][GSTRIDE];
    __shared__ __align__(16) __nv_bfloat16 Bs[3][128][GSTRIDE];

    int by = blockIdx.y;
    const __nv_bfloat16* A;
    const __nv_bfloat16* W;
    __half* C;
    const float* bptr;
    int m0;
    if (by < 16) { A = g_qb; W = g_wqb; C = g_pq; bptr = bias;    m0 = by * 128; }
    else         { A = g_kb; W = g_wkb; C = g_pk; bptr = nullptr; m0 = (by - 16) * 128; }
    int u0 = blockIdx.x * 128;

    int t = threadIdx.x;
    int w = t >> 5, lane = t & 31;
    int warpM = (w >> 2) * 64;
    int warpN = (w & 3) * 32;

    float acc[4][4][4];
#pragma unroll
    for (int mi = 0; mi < 4; mi++)
#pragma unroll
        for (int ni = 0; ni < 4; ni++)
#pragma unroll
            for (int i = 0; i < 4; i++) acc[mi][ni][i] = 0.f;

    int lrow = t >> 3, lch = t & 7;
    auto load_tile = [&](int buf, int k0) {
#pragma unroll
        for (int i = 0; i < 4; i++) {
            int row = lrow + i * 32;
            cp_async16(&As[buf][row][lch * 8], A + (size_t)(m0 + row) * 1024 + k0 + lch * 8);
            cp_async16(&Bs[buf][row][lch * 8], W + (size_t)(u0 + row) * 1024 + k0 + lch * 8);
        }
        asm volatile("cp.async.commit_group;");
    };

    load_tile(0, 0);
    load_tile(1, 64);

    int buf = 0;
    for (int it = 0; it < 16; it++) {
        if (it < 15) asm volatile("cp.async.wait_group 1;");
        else         asm volatile("cp.async.wait_group 0;");
        __syncthreads();

        if (it + 2 < 16) load_tile((buf + 2) % 3, (it + 2) * 64);

#pragma unroll
        for (int kk = 0; kk < 4; kk++) {
            unsigned a[4][4];
            int arow_l = lane & 15;
            int acol = kk * 16 + (lane >> 4) * 8;
#pragma unroll
            for (int mi = 0; mi < 4; mi++) {
                ldm_x4(a[mi][0], a[mi][1], a[mi][2], a[mi][3],
                       &As[buf][warpM + mi * 16 + arow_l][acol]);
            }
            unsigned b[4][2];
            int brow_l = ((lane >> 4) & 1) * 8 + (lane & 7);
            int bcol = kk * 16 + ((lane >> 3) & 1) * 8;
#pragma unroll
            for (int np = 0; np < 2; np++) {
                unsigned r0, r1, r2, r3;
                ldm_x4(r0, r1, r2, r3, &Bs[buf][warpN + np * 16 + brow_l][bcol]);
                b[np * 2][0] = r0; b[np * 2][1] = r1;
                b[np * 2 + 1][0] = r2; b[np * 2 + 1][1] = r3;
            }
#pragma unroll
            for (int mi = 0; mi < 4; mi++)
#pragma unroll
                for (int ni = 0; ni < 4; ni++)
                    mma16816(acc[mi][ni], a[mi], b[ni]);
        }
        buf = (buf + 1) % 3;
    }

    int g = lane >> 2, tig = lane & 3;
#pragma unroll
    for (int mi = 0; mi < 4; mi++) {
#pragma unroll
        for (int ni = 0; ni < 4; ni++) {
            int r = m0 + warpM + mi * 16 + g;
            int c = u0 + warpN + ni * 8 + tig * 2;
            float b0 = 0.f, b1 = 0.f;
            if (bptr) { b0 = __ldg(bptr + c); b1 = __ldg(bptr + c + 1); }
            *(__half2*)(C + (size_t)r * 1024 + c) =
                __floats2half2_rn(acc[mi][ni][0] + b0, acc[mi][ni][1] + b1);
            *(__half2*)(C + (size_t)(r + 8) * 1024 + c) =
                __floats2half2_rn(acc[mi][ni][2] + b0, acc[mi][ni][3] + b1);
        }
    }
}

// ---------------------------------------------------------------------------
// Kernel 2: partial scores, hybrid tanh (3/4 MUFU + 1/4 Pade on FMA pipe).
// grid (TQ/8, NB, 8); blockIdx.z = 128-u slice.
// ---------------------------------------------------------------------------
__global__ __launch_bounds__(256, 3) void k_scores3() {
    __shared__ __align__(16) __half2 pk_s[64 * 129];  // [uu][k], pad 129
    __shared__ __align__(16) __half2 pq_s[64 * 12];   // [uu][q], pad 12 (16B align)
    __shared__ __half2 v_s[64];

    int t = threadIdx.x, w = t >> 5, lane = t & 31;
    int bb = blockIdx.y;
    int qt0 = blockIdx.x * 8;
    int z = blockIdx.z;
    int u0 = z * 128;
    int kidx = (w & 3) * 32 + lane;
    int qb = (w >> 2) * 4;

#pragma unroll
    for (int i = 0; i < 8; i++) {
        int pos = t + i * 256;
        int u4 = pos & 15, tk = pos >> 4;
        uint4 d = *(const uint4*)(g_pk + (size_t)(tk * NB + bb) * 1024 + u0 + u4 * 8);
        const __half2* h = (const __half2*)&d;
#pragma unroll
        for (int j = 0; j < 4; j++) pk_s[(u4 * 4 + j) * 129 + tk] = h[j];
    }
    if (t < 128) {
        int u4 = t & 15, q = t >> 4;
        uint4 d = *(const uint4*)(g_pq + (size_t)((qt0 + q) * NB + bb) * 1024 + u0 + u4 * 8);
        const __half2* h = (const __half2*)&d;
#pragma unroll
        for (int j = 0; j < 4; j++) pq_s[(u4 * 4 + j) * 12 + q] = h[j];
    }
    if (t < 64) v_s[t] = ((const __half2*)g_vh)[u0 / 2 + t];
    __syncthreads();

    __half2 acc2[4];
#pragma unroll
    for (int j = 0; j < 4; j++) acc2[j] = __float2half2_rn(0.f);

#pragma unroll 4
    for (int uu = 0; uu < 64; uu++) {
        __half2 pk2 = pk_s[uu * 129 + kidx];
        __half2 v2 = v_s[uu];
        uint4 pq4 = *(const uint4*)&pq_s[uu * 12 + qb];   // LDS.128, broadcast
        const __half2* pqh = (const __half2*)&pq4;
#pragma unroll
        for (int j = 0; j < 4; j++) {
            __half2 a = __hadd2(pqh[j], pk2);
            __half2 th = (j == 3) ? ptanh2(a) : htanh2(a);
            acc2[j] = __hfma2(th, v2, acc2[j]);
        }
    }

#pragma unroll
    for (int j = 0; j < 4; j++) {
        int q = qt0 + qb + j;
        g_part[(((size_t)z * NB + bb) * TQ + q) * TK + kidx] =
            __low2float(acc2[j]) + __high2float(acc2[j]);
    }
}

// ---------------------------------------------------------------------------
// Kernel 3: fused reduce+softmax+context. grid (TQ/8, NB), 256 threads.
// Phase 1: warp w -> q = qt0+w softmax into smem (+optional scores out).
// Phase 2: context[tq][b][n] = sum_k p[q][k] * keys[k][b][n].
// ---------------------------------------------------------------------------
__global__ __launch_bounds__(256) void k_sm_ctx(const float* __restrict__ keys,
                                                float* __restrict__ ctx,
                                                int has_scores,
                                                float* __restrict__ scores_out) {
    __shared__ float p_s[8 * 128];
    int t = threadIdx.x, w = t >> 5, lane = t & 31;
    int bb = blockIdx.y, qt0 = blockIdx.x * 8;
    int q = qt0 + w;

    // ---- softmax phase
    float x[4];
#pragma unroll
    for (int jj = 0; jj < 4; jj++) {
        int k = lane + jj * 32;
        float s = 0.f;
#pragma unroll
        for (int z = 0; z < 8; z++)
            s += g_part[(((size_t)z * NB + bb) * TQ + q) * TK + k];
        x[jj] = s;
    }
    float m = fmaxf(fmaxf(x[0], x[1]), fmaxf(x[2], x[3]));
#pragma unroll
    for (int o = 16; o > 0; o >>= 1) m = fmaxf(m, __shfl_xor_sync(0xffffffffu, m, o));
    float e0 = __expf(x[0] - m), e1 = __expf(x[1] - m);
    float e2 = __expf(x[2] - m), e3 = __expf(x[3] - m);
    float s = e0 + e1 + e2 + e3;
#pragma unroll
    for (int o = 16; o > 0; o >>= 1) s += __shfl_xor_sync(0xffffffffu, s, o);
    float inv = __fdividef(1.f, s);
    float p0 = e0 * inv, p1 = e1 * inv, p2 = e2 * inv, p3 = e3 * inv;

    p_s[w * 128 + lane]      = p0;
    p_s[w * 128 + lane + 32] = p1;
    p_s[w * 128 + lane + 64] = p2;
    p_s[w * 128 + lane + 96] = p3;

    if (has_scores) {
        float* so = scores_out + ((size_t)q * NB + bb) * TK;
        so[lane] = p0; so[lane + 32] = p1; so[lane + 64] = p2; so[lane + 96] = p3;
    }
    __syncthreads();

    // ---- context phase: thread owns 4 n-cols (float4) for all 8 q
    float4 acc[8];
#pragma unroll
    for (int qq = 0; qq < 8; qq++) acc[qq] = make_float4(0.f, 0.f, 0.f, 0.f);

    for (int tk = 0; tk < 128; tk++) {
        float4 kv = *(const float4*)(keys + ((size_t)tk * NB + bb) * 1024 + t * 4);
#pragma unroll
        for (int qq = 0; qq < 8; qq++) {
            float pv = p_s[qq * 128 + tk];
            acc[qq].x += pv * kv.x;
            acc[qq].y += pv * kv.y;
            acc[qq].z += pv * kv.z;
            acc[qq].w += pv * kv.w;
        }
    }
#pragma unroll
    for (int qq = 0; qq < 8; qq++) {
        *(float4*)(ctx + ((size_t)(qt0 + qq) * NB + bb) * 1024 + t * 4) = acc[qq];
    }
}

// ---------------------------------------------------------------------------
extern "C" void kernel_launch(void* const* d_in, const int* in_sizes, int n_in,
                              void* d_out, int out_size) {
    const float* query = (const float*)d_in[0];
    const float* keys  = (const float*)d_in[1];
    const float* Wq    = (const float*)d_in[2];
    const float* Wk    = (const float*)d_in[3];
    const float* la    = (const float*)d_in[4];
    const float* ns    = (const float*)d_in[5];
    const float* nbias = (const float*)d_in[6];

    float* ctx = (float*)d_out;
    const int ctx_elems = TQ * NB * ND;
    const int scr_elems = TQ * NB * TK;
    int has_scores = (out_size >= ctx_elems + scr_elems) ? 1 : 0;
    float* scores = ctx + ctx_elems;

    k_convert<<<8193, 256>>>(query, keys, Wq, Wk, la, ns);

    k_gemm3<<<dim3(ND / 128, 48), 256>>>(nbias);

    k_scores3<<<dim3(TQ / 8, NB, 8), 256>>>();

    k_sm_ctx<<<dim3(TQ / 8, NB), 256>>>(keys, ctx, has_scores, scores);
}